// round 1
// baseline (speedup 1.0000x reference)
#include <cuda_runtime.h>

// ---------------------------------------------------------------------------
// BalanceLoss (OHEM-balanced BCE) on GB300.
//
// pred, gt, mask : (32,1,640,640) fp32  -> scalar fp32
//
// Key structure: neg_count = min(sum(neg), 3*pos_count). When neg_count ==
// sum(neg) (true for this data distribution), the "top-k hardest negatives"
// is simply ALL negatives, so the whole thing is 4 streaming sums. A gated
// histogram-select fallback handles the general case without costing
// anything on the fast path (the gated kernels read a flag and return).
// ---------------------------------------------------------------------------

#define THREADS 256
#define NBLOCKS 2368          // 148 SMs * 16
#define MAXBLK  4096
#define NBINS   65536

// Deterministic per-block partials (no float atomics on the main path).
__device__ float        d_posL[MAXBLK];
__device__ float        d_negL[MAXBLK];
__device__ unsigned int d_posC[MAXBLK];
__device__ unsigned int d_negC[MAXBLK];

// Fallback (top-k select) state. g_hist_* are zero at module load and are
// re-zeroed by select_kernel after any use, so state is replay-invariant.
__device__ int          g_need_select;
__device__ float        g_neg_count_target;
__device__ float        g_pos_loss_f;
__device__ float        g_pos_count_f;
__device__ unsigned int g_hist_cnt[NBINS];
__device__ float        g_hist_sum[NBINS];

// ---------------------------------------------------------------------------

__device__ __forceinline__ void accum(float p, float g, float m,
                                      float& posL, float& negL,
                                      unsigned& posC, unsigned& negC)
{
    bool pos = g > 0.5f;
    float v  = pos ? p : (1.0f - p);
    float l  = -__logf(v) * m;          // zero when masked out
    if (pos) { posL += l; posC += (m != 0.0f); }
    else     { negL += l; negC += (m != 0.0f); }
}

__global__ void __launch_bounds__(THREADS)
reduce_kernel(const float* __restrict__ pred,
              const float* __restrict__ gt,
              const float* __restrict__ mask,
              long long n)
{
    const long long n4 = n >> 2;
    const float4* p4 = reinterpret_cast<const float4*>(pred);
    const float4* g4 = reinterpret_cast<const float4*>(gt);
    const float4* m4 = reinterpret_cast<const float4*>(mask);

    float posL = 0.0f, negL = 0.0f;
    unsigned posC = 0, negC = 0;

    const long long stride = (long long)gridDim.x * blockDim.x;
    for (long long i = (long long)blockIdx.x * blockDim.x + threadIdx.x;
         i < n4; i += stride) {
        float4 p = __ldg(p4 + i);
        float4 g = __ldg(g4 + i);
        float4 m = __ldg(m4 + i);
        accum(p.x, g.x, m.x, posL, negL, posC, negC);
        accum(p.y, g.y, m.y, posL, negL, posC, negC);
        accum(p.z, g.z, m.z, posL, negL, posC, negC);
        accum(p.w, g.w, m.w, posL, negL, posC, negC);
    }
    // scalar tail (n not multiple of 4)
    if (blockIdx.x == 0 && threadIdx.x < (int)(n & 3LL)) {
        long long i = n4 * 4 + threadIdx.x;
        accum(pred[i], gt[i], mask[i], posL, negL, posC, negC);
    }

    // warp reduce
    #pragma unroll
    for (int o = 16; o > 0; o >>= 1) {
        posL += __shfl_down_sync(0xffffffffu, posL, o);
        negL += __shfl_down_sync(0xffffffffu, negL, o);
        posC += __shfl_down_sync(0xffffffffu, posC, o);
        negC += __shfl_down_sync(0xffffffffu, negC, o);
    }

    __shared__ float    wPL[THREADS / 32], wNL[THREADS / 32];
    __shared__ unsigned wPC[THREADS / 32], wNC[THREADS / 32];
    int wid = threadIdx.x >> 5;
    if ((threadIdx.x & 31) == 0) {
        wPL[wid] = posL; wNL[wid] = negL; wPC[wid] = posC; wNC[wid] = negC;
    }
    __syncthreads();
    if (threadIdx.x == 0) {
        float a = 0.0f, b = 0.0f; unsigned c = 0, d = 0;
        #pragma unroll
        for (int w = 0; w < THREADS / 32; ++w) {
            a += wPL[w]; b += wNL[w]; c += wPC[w]; d += wNC[w];
        }
        d_posL[blockIdx.x] = a;
        d_negL[blockIdx.x] = b;
        d_posC[blockIdx.x] = c;
        d_negC[blockIdx.x] = d;
    }
}

// ---------------------------------------------------------------------------

__global__ void __launch_bounds__(THREADS)
finalize_kernel(float* __restrict__ out, int nblocks)
{
    __shared__ double             sPL[THREADS], sNL[THREADS];
    __shared__ unsigned long long sPC[THREADS], sNC[THREADS];

    double pl = 0.0, nl = 0.0;
    unsigned long long pc = 0, nc = 0;
    for (int i = threadIdx.x; i < nblocks; i += blockDim.x) {
        pl += (double)d_posL[i];
        nl += (double)d_negL[i];
        pc += (unsigned long long)d_posC[i];
        nc += (unsigned long long)d_negC[i];
    }
    sPL[threadIdx.x] = pl; sNL[threadIdx.x] = nl;
    sPC[threadIdx.x] = pc; sNC[threadIdx.x] = nc;
    __syncthreads();
    for (int s = THREADS / 2; s > 0; s >>= 1) {
        if (threadIdx.x < s) {
            sPL[threadIdx.x] += sPL[threadIdx.x + s];
            sNL[threadIdx.x] += sNL[threadIdx.x + s];
            sPC[threadIdx.x] += sPC[threadIdx.x + s];
            sNC[threadIdx.x] += sNC[threadIdx.x + s];
        }
        __syncthreads();
    }

    if (threadIdx.x == 0) {
        float pos_count = (float)sPC[0];
        float neg_total = (float)sNC[0];
        float pos_loss  = (float)sPL[0];
        float neg_loss  = (float)sNL[0];
        float neg_count = fminf(neg_total, pos_count * 3.0f);

        if (neg_count > 0.0f) {
            if (neg_count >= neg_total) {
                // top-k covers all negatives -> full negative-loss sum
                out[0] = (pos_loss + neg_loss) /
                         (pos_count + neg_count + 1e-6f);
                g_need_select = 0;
            } else {
                g_need_select      = 1;
                g_neg_count_target = neg_count;
                g_pos_loss_f       = pos_loss;
                g_pos_count_f      = pos_count;
            }
        } else {
            out[0] = pos_loss / (pos_count + 1e-6f);
            g_need_select = 0;
        }
    }
}

// ---------------------------------------------------------------------------
// Fallback: 16-bit float-prefix histogram select (gated; no-op on fast path).
// For positive floats, larger bit pattern == larger value, so bin index
// (bits >> 16) is monotone in value and a high->low bin scan gives top-k.
// ---------------------------------------------------------------------------

__global__ void __launch_bounds__(THREADS)
hist_kernel(const float* __restrict__ pred,
            const float* __restrict__ gt,
            const float* __restrict__ mask,
            long long n)
{
    if (g_need_select == 0) return;
    const long long stride = (long long)gridDim.x * blockDim.x;
    for (long long i = (long long)blockIdx.x * blockDim.x + threadIdx.x;
         i < n; i += stride) {
        float m = mask[i];
        float g = gt[i];
        if (m != 0.0f && g <= 0.5f) {
            float l = -__logf(1.0f - pred[i]);
            unsigned bin = __float_as_uint(l) >> 16;
            atomicAdd(&g_hist_cnt[bin], 1u);
            atomicAdd(&g_hist_sum[bin], l);
        }
    }
}

__global__ void __launch_bounds__(256)
select_kernel(float* __restrict__ out)
{
    if (g_need_select == 0) return;

    if (threadIdx.x == 0) {
        float k = g_neg_count_target;
        double cum_sum = 0.0;
        double cum_cnt = 0.0;
        float  topk = 0.0f;
        for (int b = NBINS - 1; b >= 0; --b) {
            unsigned c = g_hist_cnt[b];
            if (c == 0) continue;
            float s = g_hist_sum[b];
            if (cum_cnt + (double)c >= (double)k) {
                float take = k - (float)cum_cnt;          // items from this bin
                topk = (float)cum_sum + take * (s / (float)c);
                break;
            }
            cum_cnt += (double)c;
            cum_sum += (double)s;
            topk = (float)cum_sum;                        // if loop exhausts
        }
        out[0] = (g_pos_loss_f + topk) /
                 (g_pos_count_f + k + 1e-6f);
    }
    __syncthreads();
    // restore histogram to zero so every graph replay sees identical state
    for (int b = threadIdx.x; b < NBINS; b += blockDim.x) {
        g_hist_cnt[b] = 0u;
        g_hist_sum[b] = 0.0f;
    }
}

// ---------------------------------------------------------------------------

extern "C" void kernel_launch(void* const* d_in, const int* in_sizes, int n_in,
                              void* d_out, int out_size)
{
    const float* pred = (const float*)d_in[0];
    const float* gt   = (const float*)d_in[1];
    const float* mask = (const float*)d_in[2];
    long long n = (long long)in_sizes[0];

    reduce_kernel<<<NBLOCKS, THREADS>>>(pred, gt, mask, n);
    finalize_kernel<<<1, THREADS>>>((float*)d_out, NBLOCKS);
    hist_kernel<<<NBLOCKS, THREADS>>>(pred, gt, mask, n);
    select_kernel<<<1, 256>>>((float*)d_out);
}

// round 2
// speedup vs baseline: 1.0633x; 1.0633x over previous
#include <cuda_runtime.h>

// ---------------------------------------------------------------------------
// BalanceLoss (OHEM-balanced BCE) on GB300, round 2.
//
// pred, gt, mask : (32,1,640,640) fp32 -> scalar fp32.
//
// R2 changes vs R1 (41.9us):
//  * finalize fused into reduce via last-block ticket (one fewer graph node)
//  * single-wave grid: 1184 blocks = 148 SMs x 8 CTAs x 256 thr
//  * __ldcs streaming loads (read-once data > L2 capacity)
// Fallback top-k (histogram select) kept as 2 flag-gated kernels; they are
// no-ops on this data distribution (neg_count == neg_total).
// ---------------------------------------------------------------------------

#define THREADS 256
#define NBLOCKS 1184          // 148 SMs * 8 CTAs -> exactly one wave @ 2048 thr/SM
#define NBINS   65536

__device__ float        d_posL[NBLOCKS];
__device__ float        d_negL[NBLOCKS];
__device__ unsigned int d_posC[NBLOCKS];
__device__ unsigned int d_negC[NBLOCKS];
__device__ unsigned int g_ticket;          // zero-init; reset by last block

// Fallback (top-k select) state.
__device__ int          g_need_select;
__device__ float        g_neg_count_target;
__device__ float        g_pos_loss_f;
__device__ float        g_pos_count_f;
__device__ unsigned int g_hist_cnt[NBINS];
__device__ float        g_hist_sum[NBINS];

// ---------------------------------------------------------------------------

__device__ __forceinline__ void accum(float p, float g, float m,
                                      float& posL, float& negL,
                                      unsigned& posC, unsigned& negC)
{
    bool pos = g > 0.5f;
    float v  = pos ? p : (1.0f - p);
    float l  = -__logf(v) * m;          // zero when masked out
    if (pos) { posL += l; posC += (m != 0.0f); }
    else     { negL += l; negC += (m != 0.0f); }
}

__global__ void __launch_bounds__(THREADS)
reduce_finalize_kernel(const float* __restrict__ pred,
                       const float* __restrict__ gt,
                       const float* __restrict__ mask,
                       long long n,
                       float* __restrict__ out)
{
    const long long n4 = n >> 2;
    const float4* p4 = reinterpret_cast<const float4*>(pred);
    const float4* g4 = reinterpret_cast<const float4*>(gt);
    const float4* m4 = reinterpret_cast<const float4*>(mask);

    float posL = 0.0f, negL = 0.0f;
    unsigned posC = 0, negC = 0;

    const long long stride = (long long)gridDim.x * blockDim.x;
    for (long long i = (long long)blockIdx.x * blockDim.x + threadIdx.x;
         i < n4; i += stride) {
        float4 p = __ldcs(p4 + i);      // evict-first: read-once stream
        float4 g = __ldcs(g4 + i);
        float4 m = __ldcs(m4 + i);
        accum(p.x, g.x, m.x, posL, negL, posC, negC);
        accum(p.y, g.y, m.y, posL, negL, posC, negC);
        accum(p.z, g.z, m.z, posL, negL, posC, negC);
        accum(p.w, g.w, m.w, posL, negL, posC, negC);
    }
    if (blockIdx.x == 0 && threadIdx.x < (int)(n & 3LL)) {
        long long i = n4 * 4 + threadIdx.x;
        accum(pred[i], gt[i], mask[i], posL, negL, posC, negC);
    }

    // intra-block reduction
    #pragma unroll
    for (int o = 16; o > 0; o >>= 1) {
        posL += __shfl_down_sync(0xffffffffu, posL, o);
        negL += __shfl_down_sync(0xffffffffu, negL, o);
        posC += __shfl_down_sync(0xffffffffu, posC, o);
        negC += __shfl_down_sync(0xffffffffu, negC, o);
    }
    __shared__ float    wPL[THREADS / 32], wNL[THREADS / 32];
    __shared__ unsigned wPC[THREADS / 32], wNC[THREADS / 32];
    int wid = threadIdx.x >> 5;
    if ((threadIdx.x & 31) == 0) {
        wPL[wid] = posL; wNL[wid] = negL; wPC[wid] = posC; wNC[wid] = negC;
    }
    __syncthreads();

    __shared__ bool is_last;
    if (threadIdx.x == 0) {
        float a = 0.0f, b = 0.0f; unsigned c = 0, d = 0;
        #pragma unroll
        for (int w = 0; w < THREADS / 32; ++w) {
            a += wPL[w]; b += wNL[w]; c += wPC[w]; d += wNC[w];
        }
        d_posL[blockIdx.x] = a;
        d_negL[blockIdx.x] = b;
        d_posC[blockIdx.x] = c;
        d_negC[blockIdx.x] = d;
        __threadfence();
        unsigned t = atomicAdd(&g_ticket, 1u);
        is_last = (t == gridDim.x - 1);
    }
    __syncthreads();
    if (!is_last) return;

    // ---- last block: finalize in double precision ----
    double pl = 0.0, nl = 0.0;
    unsigned long long pc = 0, nc = 0;
    for (int i = threadIdx.x; i < NBLOCKS; i += THREADS) {
        pl += (double)d_posL[i];
        nl += (double)d_negL[i];
        pc += (unsigned long long)d_posC[i];
        nc += (unsigned long long)d_negC[i];
    }
    __shared__ double             sPL[THREADS], sNL[THREADS];
    __shared__ unsigned long long sPC[THREADS], sNC[THREADS];
    sPL[threadIdx.x] = pl; sNL[threadIdx.x] = nl;
    sPC[threadIdx.x] = pc; sNC[threadIdx.x] = nc;
    __syncthreads();
    for (int s = THREADS / 2; s > 0; s >>= 1) {
        if (threadIdx.x < s) {
            sPL[threadIdx.x] += sPL[threadIdx.x + s];
            sNL[threadIdx.x] += sNL[threadIdx.x + s];
            sPC[threadIdx.x] += sPC[threadIdx.x + s];
            sNC[threadIdx.x] += sNC[threadIdx.x + s];
        }
        __syncthreads();
    }

    if (threadIdx.x == 0) {
        g_ticket = 0;                          // reset for next graph replay

        float pos_count = (float)sPC[0];
        float neg_total = (float)sNC[0];
        float pos_loss  = (float)sPL[0];
        float neg_loss  = (float)sNL[0];
        float neg_count = fminf(neg_total, pos_count * 3.0f);

        if (neg_count > 0.0f) {
            if (neg_count >= neg_total) {
                out[0] = (pos_loss + neg_loss) /
                         (pos_count + neg_count + 1e-6f);
                g_need_select = 0;
            } else {
                g_need_select      = 1;
                g_neg_count_target = neg_count;
                g_pos_loss_f       = pos_loss;
                g_pos_count_f      = pos_count;
            }
        } else {
            out[0] = pos_loss / (pos_count + 1e-6f);
            g_need_select = 0;
        }
    }
}

// ---------------------------------------------------------------------------
// Gated fallback: 16-bit float-prefix histogram top-k. No-op on fast path.
// ---------------------------------------------------------------------------

__global__ void __launch_bounds__(THREADS)
hist_kernel(const float* __restrict__ pred,
            const float* __restrict__ gt,
            const float* __restrict__ mask,
            long long n)
{
    if (g_need_select == 0) return;
    const long long stride = (long long)gridDim.x * blockDim.x;
    for (long long i = (long long)blockIdx.x * blockDim.x + threadIdx.x;
         i < n; i += stride) {
        float m = mask[i];
        float g = gt[i];
        if (m != 0.0f && g <= 0.5f) {
            float l = -__logf(1.0f - pred[i]);
            unsigned bin = __float_as_uint(l) >> 16;
            atomicAdd(&g_hist_cnt[bin], 1u);
            atomicAdd(&g_hist_sum[bin], l);
        }
    }
}

__global__ void __launch_bounds__(256)
select_kernel(float* __restrict__ out)
{
    if (g_need_select == 0) return;

    if (threadIdx.x == 0) {
        float k = g_neg_count_target;
        double cum_sum = 0.0;
        double cum_cnt = 0.0;
        float  topk = 0.0f;
        for (int b = NBINS - 1; b >= 0; --b) {
            unsigned c = g_hist_cnt[b];
            if (c == 0) continue;
            float s = g_hist_sum[b];
            if (cum_cnt + (double)c >= (double)k) {
                float take = k - (float)cum_cnt;
                topk = (float)cum_sum + take * (s / (float)c);
                break;
            }
            cum_cnt += (double)c;
            cum_sum += (double)s;
            topk = (float)cum_sum;
        }
        out[0] = (g_pos_loss_f + topk) /
                 (g_pos_count_f + k + 1e-6f);
    }
    __syncthreads();
    for (int b = threadIdx.x; b < NBINS; b += blockDim.x) {
        g_hist_cnt[b] = 0u;
        g_hist_sum[b] = 0.0f;
    }
}

// ---------------------------------------------------------------------------

extern "C" void kernel_launch(void* const* d_in, const int* in_sizes, int n_in,
                              void* d_out, int out_size)
{
    const float* pred = (const float*)d_in[0];
    const float* gt   = (const float*)d_in[1];
    const float* mask = (const float*)d_in[2];
    long long n = (long long)in_sizes[0];

    reduce_finalize_kernel<<<NBLOCKS, THREADS>>>(pred, gt, mask, n,
                                                 (float*)d_out);
    hist_kernel<<<NBLOCKS, THREADS>>>(pred, gt, mask, n);
    select_kernel<<<1, 256>>>((float*)d_out);
}

// round 3
// speedup vs baseline: 1.2096x; 1.1376x over previous
#include <cuda_runtime.h>

// ---------------------------------------------------------------------------
// BalanceLoss (OHEM-balanced BCE) on GB300, round 3.
//
// R3 vs R2 (39.4us, kernel 35.6us @ 57% DRAM):
//  * branch-free FMA body: v = fma(g, 2p-1, 1-p); single loss sum S=sum m*lg2(v)
//    (total loss = -ln2*S; fast path never needs the pos/neg loss split)
//  * 592 blocks x 256thr, __launch_bounds__(256,4): guaranteed single wave,
//    64-reg budget (R2 silently fell to 7 CTAs/SM -> 148-block tail wave)
//  * unroll-2 with all 6 float4 loads batched -> MLP 6
//  * fallback hist+select merged into ONE gated kernel (ticket sync)
// ---------------------------------------------------------------------------

#define THREADS 256
#define NBLOCKS 592           // 148 SMs x 4 CTAs (<= one wave on 152-SM GB300 too)
#define NBINS   65536

__device__ float        d_S[NBLOCKS];   // sum of m * lg2(v)   (negative)
__device__ float        d_P[NBLOCKS];   // sum of g * m        (pos count)
__device__ float        d_C[NBLOCKS];   // sum of m            (mask count)
__device__ unsigned int g_ticket;       // zero-init; reset by last block

// Fallback (top-k select) state — untouched on the fast path.
__device__ int          g_need_select;
__device__ float        g_k_target;     // neg_count = 3*pos_count
__device__ float        g_pos_count;
__device__ float        g_pos_loss;     // accumulated by fallback
__device__ unsigned int g_fb_ticket;
__device__ unsigned int g_hist_cnt[NBINS];
__device__ float        g_hist_sum[NBINS];

// ---------------------------------------------------------------------------

__device__ __forceinline__ void body(const float4& p, const float4& g,
                                     const float4& m,
                                     float& S, float& P, float& C)
{
#define ONE(px, gx, mx)                                     \
    {                                                       \
        float t = 1.0f - (px);                              \
        float u = (px) - t;               /* 2p - 1 */      \
        float v = fmaf((gx), u, t);       /* g?p:1-p */     \
        float l = __log2f(v);                               \
        S = fmaf((mx), l, S);                               \
        P = fmaf((gx), (mx), P);                            \
        C += (mx);                                          \
    }
    ONE(p.x, g.x, m.x) ONE(p.y, g.y, m.y)
    ONE(p.z, g.z, m.z) ONE(p.w, g.w, m.w)
#undef ONE
}

__global__ void __launch_bounds__(THREADS, 4)
reduce_finalize_kernel(const float* __restrict__ pred,
                       const float* __restrict__ gt,
                       const float* __restrict__ mask,
                       long long n,
                       float* __restrict__ out)
{
    const long long n4 = n >> 2;
    const float4* p4 = reinterpret_cast<const float4*>(pred);
    const float4* g4 = reinterpret_cast<const float4*>(gt);
    const float4* m4 = reinterpret_cast<const float4*>(mask);

    float S = 0.0f, P = 0.0f, C = 0.0f;

    const long long stride = (long long)gridDim.x * blockDim.x;
    long long i = (long long)blockIdx.x * blockDim.x + threadIdx.x;

    // unroll-2: batch all 6 float4 loads before consuming (MLP=6)
    for (; i + stride < n4; i += 2 * stride) {
        float4 pa = __ldcs(p4 + i);
        float4 pb = __ldcs(p4 + i + stride);
        float4 ga = __ldcs(g4 + i);
        float4 gb = __ldcs(g4 + i + stride);
        float4 ma = __ldcs(m4 + i);
        float4 mb = __ldcs(m4 + i + stride);
        body(pa, ga, ma, S, P, C);
        body(pb, gb, mb, S, P, C);
    }
    if (i < n4) {
        float4 pa = __ldcs(p4 + i);
        float4 ga = __ldcs(g4 + i);
        float4 ma = __ldcs(m4 + i);
        body(pa, ga, ma, S, P, C);
    }
    // scalar tail (n not multiple of 4) — n is divisible here; kept for safety
    if (blockIdx.x == 0 && threadIdx.x < (int)(n & 3LL)) {
        long long j = n4 * 4 + threadIdx.x;
        float p = pred[j], g = gt[j], m = mask[j];
        float t = 1.0f - p;
        float v = fmaf(g, p - t, t);
        S = fmaf(m, __log2f(v), S);
        P = fmaf(g, m, P);
        C += m;
    }

    // intra-block reduction
    #pragma unroll
    for (int o = 16; o > 0; o >>= 1) {
        S += __shfl_down_sync(0xffffffffu, S, o);
        P += __shfl_down_sync(0xffffffffu, P, o);
        C += __shfl_down_sync(0xffffffffu, C, o);
    }
    __shared__ float wS[THREADS / 32], wP[THREADS / 32], wC[THREADS / 32];
    int wid = threadIdx.x >> 5;
    if ((threadIdx.x & 31) == 0) { wS[wid] = S; wP[wid] = P; wC[wid] = C; }
    __syncthreads();

    __shared__ bool is_last;
    if (threadIdx.x == 0) {
        float a = 0.0f, b = 0.0f, c = 0.0f;
        #pragma unroll
        for (int w = 0; w < THREADS / 32; ++w) {
            a += wS[w]; b += wP[w]; c += wC[w];
        }
        d_S[blockIdx.x] = a;
        d_P[blockIdx.x] = b;
        d_C[blockIdx.x] = c;
        __threadfence();
        unsigned t = atomicAdd(&g_ticket, 1u);
        is_last = (t == gridDim.x - 1);
    }
    __syncthreads();
    if (!is_last) return;

    // ---- last block: finalize in double precision ----
    double sS = 0.0, sP = 0.0, sC = 0.0;
    for (int k = threadIdx.x; k < NBLOCKS; k += THREADS) {
        sS += (double)d_S[k];
        sP += (double)d_P[k];
        sC += (double)d_C[k];
    }
    __shared__ double rS[THREADS], rP[THREADS], rC[THREADS];
    rS[threadIdx.x] = sS; rP[threadIdx.x] = sP; rC[threadIdx.x] = sC;
    __syncthreads();
    for (int s = THREADS / 2; s > 0; s >>= 1) {
        if (threadIdx.x < s) {
            rS[threadIdx.x] += rS[threadIdx.x + s];
            rP[threadIdx.x] += rP[threadIdx.x + s];
            rC[threadIdx.x] += rC[threadIdx.x + s];
        }
        __syncthreads();
    }

    if (threadIdx.x == 0) {
        g_ticket = 0;                                   // replay-invariant

        const double LN2 = 0.6931471805599453;
        double total_loss = -LN2 * rS[0];               // pos_loss + neg_loss
        float  pos_count  = (float)rP[0];
        float  mask_count = (float)rC[0];
        float  neg_total  = mask_count - pos_count;
        float  neg_count  = fminf(neg_total, pos_count * 3.0f);

        if (neg_count > 0.0f) {
            if (neg_count >= neg_total) {
                // top-k covers all negatives -> total loss / total count
                out[0] = (float)(total_loss /
                                 (double)(pos_count + neg_count + 1e-6f));
                g_need_select = 0;
            } else {
                g_need_select = 1;
                g_k_target    = neg_count;
                g_pos_count   = pos_count;
            }
        } else {
            // neg_count == 0: either no positives (pos_loss==0 -> 0) or no
            // negatives (total_loss == pos_loss)
            out[0] = (pos_count > 0.0f)
                   ? (float)(total_loss / (double)(pos_count + 1e-6f))
                   : 0.0f;
            g_need_select = 0;
        }
    }
}

// ---------------------------------------------------------------------------
// Gated fallback (single kernel): recompute pos_loss + histogram of negative
// losses, then last block scans bins high->low for the top-k sum. No-op on
// the fast path. 16-bit float-prefix bins are monotone for positive floats.
// ---------------------------------------------------------------------------

__global__ void __launch_bounds__(THREADS)
fallback_kernel(const float* __restrict__ pred,
                const float* __restrict__ gt,
                const float* __restrict__ mask,
                long long n,
                float* __restrict__ out)
{
    if (g_need_select == 0) return;

    float posL = 0.0f;
    const long long stride = (long long)gridDim.x * blockDim.x;
    for (long long i = (long long)blockIdx.x * blockDim.x + threadIdx.x;
         i < n; i += stride) {
        float m = mask[i];
        if (m == 0.0f) continue;
        float g = gt[i];
        float p = pred[i];
        if (g > 0.5f) {
            posL += -__logf(p);
        } else {
            float l = -__logf(1.0f - p);
            unsigned bin = __float_as_uint(l) >> 16;
            atomicAdd(&g_hist_cnt[bin], 1u);
            atomicAdd(&g_hist_sum[bin], l);
        }
    }

    // block-reduce posL, one atomic per block
    #pragma unroll
    for (int o = 16; o > 0; o >>= 1)
        posL += __shfl_down_sync(0xffffffffu, posL, o);
    __shared__ float wL[THREADS / 32];
    int wid = threadIdx.x >> 5;
    if ((threadIdx.x & 31) == 0) wL[wid] = posL;
    __syncthreads();

    __shared__ bool is_last;
    if (threadIdx.x == 0) {
        float a = 0.0f;
        #pragma unroll
        for (int w = 0; w < THREADS / 32; ++w) a += wL[w];
        atomicAdd(&g_pos_loss, a);
        __threadfence();
        unsigned t = atomicAdd(&g_fb_ticket, 1u);
        is_last = (t == gridDim.x - 1);
    }
    __syncthreads();
    if (!is_last) return;

    if (threadIdx.x == 0) {
        float  k = g_k_target;
        double cum_sum = 0.0, cum_cnt = 0.0;
        float  topk = 0.0f;
        for (int b = NBINS - 1; b >= 0; --b) {
            unsigned c = g_hist_cnt[b];
            if (c == 0) continue;
            float s = g_hist_sum[b];
            if (cum_cnt + (double)c >= (double)k) {
                float take = k - (float)cum_cnt;
                topk = (float)cum_sum + take * (s / (float)c);
                break;
            }
            cum_cnt += (double)c;
            cum_sum += (double)s;
            topk = (float)cum_sum;
        }
        out[0] = (g_pos_loss + topk) / (g_pos_count + k + 1e-6f);
        g_fb_ticket = 0;
        g_pos_loss  = 0.0f;
    }
    __syncthreads();
    for (int b = threadIdx.x; b < NBINS; b += blockDim.x) {
        g_hist_cnt[b] = 0u;
        g_hist_sum[b] = 0.0f;
    }
}

// ---------------------------------------------------------------------------

extern "C" void kernel_launch(void* const* d_in, const int* in_sizes, int n_in,
                              void* d_out, int out_size)
{
    const float* pred = (const float*)d_in[0];
    const float* gt   = (const float*)d_in[1];
    const float* mask = (const float*)d_in[2];
    long long n = (long long)in_sizes[0];

    reduce_finalize_kernel<<<NBLOCKS, THREADS>>>(pred, gt, mask, n,
                                                 (float*)d_out);
    fallback_kernel<<<NBLOCKS, THREADS>>>(pred, gt, mask, n, (float*)d_out);
}

// round 4
// speedup vs baseline: 1.2743x; 1.0535x over previous
#include <cuda_runtime.h>

// ---------------------------------------------------------------------------
// BalanceLoss (OHEM-balanced BCE) on GB300, round 4.
//
// R4 vs R3 (34.7us): SINGLE kernel node. The gated fallback kernel cost a
// flat ~4.4us of launch overhead even as a no-op; instead, the last block of
// the main kernel runs the (never-taken on this data) top-k select path
// itself. Plus unroll-3 batched loads (9 float4 in flight per thread).
// ---------------------------------------------------------------------------

#define THREADS 256
#define NBLOCKS 592           // 148 SMs x 4 CTAs; single wave (also on 152 SMs)
#define NBINS   65536

__device__ float        d_S[NBLOCKS];   // sum of m * lg2(v)   (negative)
__device__ float        d_P[NBLOCKS];   // sum of g * m        (pos count)
__device__ float        d_C[NBLOCKS];   // sum of m            (mask count)
__device__ unsigned int g_ticket;       // zero-init; reset by last block

// Slow-path (top-k select) scratch — only touched if 3*pos < neg_total.
__device__ unsigned int g_hist_cnt[NBINS];
__device__ float        g_hist_sum[NBINS];

// ---------------------------------------------------------------------------

__device__ __forceinline__ void body(const float4& p, const float4& g,
                                     const float4& m,
                                     float& S, float& P, float& C)
{
#define ONE(px, gx, mx)                                     \
    {                                                       \
        float t = 1.0f - (px);                              \
        float u = (px) - t;               /* 2p - 1 */      \
        float v = fmaf((gx), u, t);       /* g?p:1-p */     \
        float l = __log2f(v);                               \
        S = fmaf((mx), l, S);                               \
        P = fmaf((gx), (mx), P);                            \
        C += (mx);                                          \
    }
    ONE(p.x, g.x, m.x) ONE(p.y, g.y, m.y)
    ONE(p.z, g.z, m.z) ONE(p.w, g.w, m.w)
#undef ONE
}

__global__ void __launch_bounds__(THREADS, 4)
balance_loss_kernel(const float* __restrict__ pred,
                    const float* __restrict__ gt,
                    const float* __restrict__ mask,
                    long long n,
                    float* __restrict__ out)
{
    const long long n4 = n >> 2;
    const float4* p4 = reinterpret_cast<const float4*>(pred);
    const float4* g4 = reinterpret_cast<const float4*>(gt);
    const float4* m4 = reinterpret_cast<const float4*>(mask);

    float S = 0.0f, P = 0.0f, C = 0.0f;

    const long long stride = (long long)gridDim.x * blockDim.x;
    long long i = (long long)blockIdx.x * blockDim.x + threadIdx.x;

    // unroll-3: batch all 9 float4 loads before consuming (MLP=9)
    for (; i + 2 * stride < n4; i += 3 * stride) {
        float4 pa = __ldcs(p4 + i);
        float4 pb = __ldcs(p4 + i + stride);
        float4 pc = __ldcs(p4 + i + 2 * stride);
        float4 ga = __ldcs(g4 + i);
        float4 gb = __ldcs(g4 + i + stride);
        float4 gc = __ldcs(g4 + i + 2 * stride);
        float4 ma = __ldcs(m4 + i);
        float4 mb = __ldcs(m4 + i + stride);
        float4 mc = __ldcs(m4 + i + 2 * stride);
        body(pa, ga, ma, S, P, C);
        body(pb, gb, mb, S, P, C);
        body(pc, gc, mc, S, P, C);
    }
    for (; i < n4; i += stride) {
        float4 pa = __ldcs(p4 + i);
        float4 ga = __ldcs(g4 + i);
        float4 ma = __ldcs(m4 + i);
        body(pa, ga, ma, S, P, C);
    }
    // scalar tail (n not multiple of 4)
    if (blockIdx.x == 0 && threadIdx.x < (int)(n & 3LL)) {
        long long j = n4 * 4 + threadIdx.x;
        float p = pred[j], g = gt[j], m = mask[j];
        float t = 1.0f - p;
        float v = fmaf(g, p - t, t);
        S = fmaf(m, __log2f(v), S);
        P = fmaf(g, m, P);
        C += m;
    }

    // ---- intra-block reduction ----
    #pragma unroll
    for (int o = 16; o > 0; o >>= 1) {
        S += __shfl_down_sync(0xffffffffu, S, o);
        P += __shfl_down_sync(0xffffffffu, P, o);
        C += __shfl_down_sync(0xffffffffu, C, o);
    }
    __shared__ float wS[THREADS / 32], wP[THREADS / 32], wC[THREADS / 32];
    int wid = threadIdx.x >> 5;
    if ((threadIdx.x & 31) == 0) { wS[wid] = S; wP[wid] = P; wC[wid] = C; }
    __syncthreads();

    __shared__ bool is_last;
    if (threadIdx.x == 0) {
        float a = 0.0f, b = 0.0f, c = 0.0f;
        #pragma unroll
        for (int w = 0; w < THREADS / 32; ++w) {
            a += wS[w]; b += wP[w]; c += wC[w];
        }
        d_S[blockIdx.x] = a;
        d_P[blockIdx.x] = b;
        d_C[blockIdx.x] = c;
        __threadfence();
        unsigned t = atomicAdd(&g_ticket, 1u);
        is_last = (t == gridDim.x - 1);
    }
    __syncthreads();
    if (!is_last) return;

    // ---- last block: finalize in double precision ----
    double sS = 0.0, sP = 0.0, sC = 0.0;
    for (int k = threadIdx.x; k < NBLOCKS; k += THREADS) {
        sS += (double)d_S[k];
        sP += (double)d_P[k];
        sC += (double)d_C[k];
    }
    __shared__ double rS[THREADS], rP[THREADS], rC[THREADS];
    rS[threadIdx.x] = sS; rP[threadIdx.x] = sP; rC[threadIdx.x] = sC;
    __syncthreads();
    for (int s = THREADS / 2; s > 0; s >>= 1) {
        if (threadIdx.x < s) {
            rS[threadIdx.x] += rS[threadIdx.x + s];
            rP[threadIdx.x] += rP[threadIdx.x + s];
            rC[threadIdx.x] += rC[threadIdx.x + s];
        }
        __syncthreads();
    }

    __shared__ int   need_select;
    __shared__ float sh_pos_count, sh_k_target;
    if (threadIdx.x == 0) {
        g_ticket = 0;                                   // replay-invariant

        const double LN2 = 0.6931471805599453;
        double total_loss = -LN2 * rS[0];               // pos_loss + neg_loss
        float  pos_count  = (float)rP[0];
        float  mask_count = (float)rC[0];
        float  neg_total  = mask_count - pos_count;
        float  neg_count  = fminf(neg_total, pos_count * 3.0f);

        need_select = 0;
        if (neg_count > 0.0f) {
            if (neg_count >= neg_total) {
                // top-k covers all negatives -> total loss / total count
                out[0] = (float)(total_loss /
                                 (double)(pos_count + neg_count + 1e-6f));
            } else {
                need_select  = 1;
                sh_pos_count = pos_count;
                sh_k_target  = neg_count;
            }
        } else {
            out[0] = (pos_count > 0.0f)
                   ? (float)(total_loss / (double)(pos_count + 1e-6f))
                   : 0.0f;
        }
    }
    __syncthreads();
    if (!need_select) return;

    // -----------------------------------------------------------------------
    // Slow path (never taken when neg_total <= 3*pos): this single block
    // re-reads the inputs, builds a 16-bit float-prefix histogram of negative
    // losses (monotone bins for positive floats), recomputes pos_loss, and
    // scans bins high->low for the top-k sum. Correctness-only path.
    // -----------------------------------------------------------------------
    float posL = 0.0f;
    for (long long j = threadIdx.x; j < n; j += THREADS) {
        float m = mask[j];
        if (m == 0.0f) continue;
        float g = gt[j];
        float p = pred[j];
        if (g > 0.5f) {
            posL += -__logf(p);
        } else {
            float l = -__logf(1.0f - p);
            unsigned bin = __float_as_uint(l) >> 16;
            atomicAdd(&g_hist_cnt[bin], 1u);
            atomicAdd(&g_hist_sum[bin], l);
        }
    }
    // reduce posL across the block (reuse rS)
    #pragma unroll
    for (int o = 16; o > 0; o >>= 1)
        posL += __shfl_down_sync(0xffffffffu, posL, o);
    if ((threadIdx.x & 31) == 0) rS[threadIdx.x >> 5] = (double)posL;
    __syncthreads();

    if (threadIdx.x == 0) {
        double pos_loss = 0.0;
        #pragma unroll
        for (int w = 0; w < THREADS / 32; ++w) pos_loss += rS[w];

        float  k = sh_k_target;
        double cum_sum = 0.0, cum_cnt = 0.0;
        float  topk = 0.0f;
        for (int b = NBINS - 1; b >= 0; --b) {
            unsigned c = g_hist_cnt[b];
            if (c == 0) continue;
            float s = g_hist_sum[b];
            if (cum_cnt + (double)c >= (double)k) {
                float take = k - (float)cum_cnt;
                topk = (float)cum_sum + take * (s / (float)c);
                break;
            }
            cum_cnt += (double)c;
            cum_sum += (double)s;
            topk = (float)cum_sum;
        }
        out[0] = ((float)pos_loss + topk) / (sh_pos_count + k + 1e-6f);
    }
    __syncthreads();
    // restore histogram scratch so every replay sees identical state
    for (int b = threadIdx.x; b < NBINS; b += THREADS) {
        g_hist_cnt[b] = 0u;
        g_hist_sum[b] = 0.0f;
    }
}

// ---------------------------------------------------------------------------

extern "C" void kernel_launch(void* const* d_in, const int* in_sizes, int n_in,
                              void* d_out, int out_size)
{
    const float* pred = (const float*)d_in[0];
    const float* gt   = (const float*)d_in[1];
    const float* mask = (const float*)d_in[2];
    long long n = (long long)in_sizes[0];

    balance_loss_kernel<<<NBLOCKS, THREADS>>>(pred, gt, mask, n,
                                              (float*)d_out);
}